// round 2
// baseline (speedup 1.0000x reference)
#include <cuda_runtime.h>

// ---------------------------------------------------------------------------
// BaselineGNN: 4-layer GCN inference.
//  Pipeline per launch:
//   1. degree histogram (int atomics) -> dinv = rsqrt(deg+1)
//   2. CSR build by dst: exclusive scan + scatter (edge weight precomputed)
//   3. h = relu(x @ W_in + b_in)          [fp32 SIMT GEMM, fused bias+relu]
//   4. 4x { hw = h @ Ws[l];  h = relu(BN(gather_csr(hw) + hw*selfw + b)) }
//   5. mean-pool by graph (atomics), 2-layer MLP head
//  All scratch lives in __device__ globals (no allocation).  Kernels reference
//  the globals directly (no cudaGetSymbolAddress in kernel_launch).
// ---------------------------------------------------------------------------

namespace {
constexpr int NMAX  = 100000;
constexpr int EMAX  = 1600000;
constexpr int HDIM  = 128;
constexpr int GMAX  = 256;
constexpr int LAYERS = 4;
constexpr float EPSV = 1e-5f;
}

__device__ float g_h [NMAX * HDIM];
__device__ float g_hw[NMAX * HDIM];
__device__ int   g_degc[NMAX];
__device__ float g_dinv[NMAX];
__device__ int   g_off[NMAX];
__device__ int   g_cur[NMAX];
__device__ int   g_bsums[128];
__device__ int   g_csr_src[EMAX];
__device__ float g_csr_w[EMAX];
__device__ float g_sums[GMAX * HDIM];
__device__ float g_cnts[GMAX];

// ---------------------------------------------------------------------------

__global__ void k_zero_deg(int n) {
    int i = blockIdx.x * blockDim.x + threadIdx.x;
    if (i < n) g_degc[i] = 0;
}

__global__ void k_hist(const int* __restrict__ dst, int e) {
    int i = blockIdx.x * blockDim.x + threadIdx.x;
    if (i < e) atomicAdd(&g_degc[dst[i]], 1);
}

__global__ void k_dinv(int n) {
    int i = blockIdx.x * blockDim.x + threadIdx.x;
    if (i < n) g_dinv[i] = rsqrtf((float)(g_degc[i] + 1));
}

// exclusive scan of g_degc -> g_off  (3-kernel scan)
__global__ void k_scan1(int n) {
    __shared__ int tmp[1024];
    int gid = blockIdx.x * 1024 + threadIdx.x;
    int v = (gid < n) ? g_degc[gid] : 0;
    tmp[threadIdx.x] = v;
    __syncthreads();
    for (int d = 1; d < 1024; d <<= 1) {
        int t = (threadIdx.x >= d) ? tmp[threadIdx.x - d] : 0;
        __syncthreads();
        tmp[threadIdx.x] += t;
        __syncthreads();
    }
    if (gid < n) g_off[gid] = tmp[threadIdx.x] - v;   // exclusive
    if (threadIdx.x == 1023) g_bsums[blockIdx.x] = tmp[1023];
}

__global__ void k_scan2(int nb) {
    __shared__ int s[128];
    int tid = threadIdx.x;
    if (tid < nb) s[tid] = g_bsums[tid];
    __syncthreads();
    if (tid == 0) {
        int run = 0;
        for (int i = 0; i < nb; i++) { int t = s[i]; s[i] = run; run += t; }
    }
    __syncthreads();
    if (tid < nb) g_bsums[tid] = s[tid];
}

__global__ void k_scan3(int n) {
    int gid = blockIdx.x * 1024 + threadIdx.x;
    if (gid < n) {
        int v = g_off[gid] + g_bsums[blockIdx.x];
        g_off[gid] = v;
        g_cur[gid] = v;
    }
}

__global__ void k_scatter(const int* __restrict__ src, const int* __restrict__ dst, int e) {
    int i = blockIdx.x * blockDim.x + threadIdx.x;
    if (i < e) {
        int d = dst[i], s = src[i];
        int p = atomicAdd(&g_cur[d], 1);
        g_csr_src[p] = s;
        g_csr_w[p]   = g_dinv[s] * g_dinv[d];
    }
}

// ---------------------------------------------------------------------------
// fp32 SGEMM:  C[M,128] = A[M,128] @ B[128,128] (+bias)(relu)
// BM=128, BN=128, BK=16, 256 threads, 8x8 per thread.
// MODE 0: A = x param, C = g_h, bias+relu.   MODE 1: A = g_h, C = g_hw, plain.
// ---------------------------------------------------------------------------
template <int MODE>
__global__ void k_gemm(const float* __restrict__ Ap, const float* __restrict__ B,
                       const float* __restrict__ bias, int M) {
    const float* A = (MODE == 0) ? Ap : g_h;
    float*       C = (MODE == 0) ? g_h : g_hw;
    __shared__ float As[16][132];   // [k][m], padded
    __shared__ float Bs[16][128];   // [k][n]
    int tid = threadIdx.x;
    int tx = tid & 15;         // col group 0..15
    int ty = tid >> 4;         // row group 0..15
    int row0 = blockIdx.x * 128;
    float acc[8][8];
#pragma unroll
    for (int i = 0; i < 8; i++)
#pragma unroll
        for (int j = 0; j < 8; j++) acc[i][j] = 0.f;

    for (int k0 = 0; k0 < 128; k0 += 16) {
#pragma unroll
        for (int t = 0; t < 2; t++) {
            int idx = tid * 2 + t;
            int r  = idx >> 2;
            int kk = (idx & 3) * 4;
            float4 v = make_float4(0.f, 0.f, 0.f, 0.f);
            if (row0 + r < M)
                v = *(const float4*)&A[(size_t)(row0 + r) * 128 + k0 + kk];
            As[kk + 0][r] = v.x; As[kk + 1][r] = v.y;
            As[kk + 2][r] = v.z; As[kk + 3][r] = v.w;
        }
#pragma unroll
        for (int t = 0; t < 2; t++) {
            int idx = tid * 2 + t;
            int kk = idx >> 5;
            int c  = (idx & 31) * 4;
            *(float4*)&Bs[kk][c] = *(const float4*)&B[(size_t)(k0 + kk) * 128 + c];
        }
        __syncthreads();
#pragma unroll
        for (int kk = 0; kk < 16; kk++) {
            float a[8], b[8];
            *(float4*)&a[0] = *(const float4*)&As[kk][ty * 8];
            *(float4*)&a[4] = *(const float4*)&As[kk][ty * 8 + 4];
            *(float4*)&b[0] = *(const float4*)&Bs[kk][tx * 8];
            *(float4*)&b[4] = *(const float4*)&Bs[kk][tx * 8 + 4];
#pragma unroll
            for (int i = 0; i < 8; i++)
#pragma unroll
                for (int j = 0; j < 8; j++) acc[i][j] += a[i] * b[j];
        }
        __syncthreads();
    }
#pragma unroll
    for (int i = 0; i < 8; i++) {
        int r = row0 + ty * 8 + i;
        if (r < M) {
#pragma unroll
            for (int j = 0; j < 8; j += 4) {
                int c = tx * 8 + j;
                float4 v = make_float4(acc[i][j], acc[i][j + 1], acc[i][j + 2], acc[i][j + 3]);
                if (MODE == 0) {
                    v.x += bias[c];     v.y += bias[c + 1];
                    v.z += bias[c + 2]; v.w += bias[c + 3];
                    v.x = fmaxf(v.x, 0.f); v.y = fmaxf(v.y, 0.f);
                    v.z = fmaxf(v.z, 0.f); v.w = fmaxf(v.w, 0.f);
                }
                *(float4*)&C[(size_t)r * 128 + c] = v;
            }
        }
    }
}

// ---------------------------------------------------------------------------
// CSR gather + self-loop + bias + BN(eval) + relu.  One warp per node;
// each lane owns 4 consecutive features (float4).  Reads g_hw, writes g_h.
// ---------------------------------------------------------------------------
__global__ void k_agg(const float* __restrict__ bias,
                      const float* __restrict__ gamma,
                      const float* __restrict__ beta,
                      const float* __restrict__ rmean,
                      const float* __restrict__ rvar,
                      int n, int e) {
    int w    = (blockIdx.x * blockDim.x + threadIdx.x) >> 5;
    int lane = threadIdx.x & 31;
    if (w >= n) return;
    int f = lane * 4;
    const float* hw = g_hw;

    float dv = g_dinv[w];
    float ws = dv * dv;
    float4 hv = *(const float4*)(hw + (size_t)w * HDIM + f);
    float ax = hv.x * ws, ay = hv.y * ws, az = hv.z * ws, aw = hv.w * ws;

    int j0 = g_off[w];
    int j1 = (w + 1 < n) ? g_off[w + 1] : e;
    for (int j = j0; j < j1; j++) {
        int   s  = g_csr_src[j];
        float wt = g_csr_w[j];
        float4 v = *(const float4*)(hw + (size_t)s * HDIM + f);
        ax += v.x * wt; ay += v.y * wt; az += v.z * wt; aw += v.w * wt;
    }

    float4 bb = *(const float4*)(bias  + f);
    float4 gm = *(const float4*)(gamma + f);
    float4 bt = *(const float4*)(beta  + f);
    float4 rm = *(const float4*)(rmean + f);
    float4 rv = *(const float4*)(rvar  + f);
    float4 o;
    o.x = fmaxf((ax + bb.x - rm.x) * rsqrtf(rv.x + EPSV) * gm.x + bt.x, 0.f);
    o.y = fmaxf((ay + bb.y - rm.y) * rsqrtf(rv.y + EPSV) * gm.y + bt.y, 0.f);
    o.z = fmaxf((az + bb.z - rm.z) * rsqrtf(rv.z + EPSV) * gm.z + bt.z, 0.f);
    o.w = fmaxf((aw + bb.w - rm.w) * rsqrtf(rv.w + EPSV) * gm.w + bt.w, 0.f);
    *(float4*)(g_h + (size_t)w * HDIM + f) = o;
}

// ---------------------------------------------------------------------------

__global__ void k_zero_pool() {
    int i = blockIdx.x * blockDim.x + threadIdx.x;
    if (i < GMAX * HDIM) g_sums[i] = 0.f;
    if (i < GMAX)        g_cnts[i] = 0.f;
}

__global__ void k_pool(const int* __restrict__ batch, int n) {
    int w    = (blockIdx.x * blockDim.x + threadIdx.x) >> 5;
    int lane = threadIdx.x & 31;
    if (w >= n) return;
    int g = batch[w];
    int f = lane * 4;
    float4 v = *(const float4*)(g_h + (size_t)w * HDIM + f);
    atomicAdd(&g_sums[g * HDIM + f + 0], v.x);
    atomicAdd(&g_sums[g * HDIM + f + 1], v.y);
    atomicAdd(&g_sums[g * HDIM + f + 2], v.z);
    atomicAdd(&g_sums[g * HDIM + f + 3], v.w);
    if (lane == 0) atomicAdd(&g_cnts[g], 1.f);
}

// head: ge = sums/cnt ; relu(ge@fc1 + b1) @ fc2 + b2.  One block/graph.
__global__ void k_head(const float* __restrict__ fc1w, const float* __restrict__ fc1b,
                       const float* __restrict__ fc2w, const float* __restrict__ fc2b,
                       float* __restrict__ out) {
    int g = blockIdx.x;
    int tid = threadIdx.x;   // 64 threads
    __shared__ float ge[HDIM];
    __shared__ float h1[64];
    float cnt = fmaxf(g_cnts[g], 1.f);
    float inv = 1.f / cnt;
    for (int i = tid; i < HDIM; i += 64) ge[i] = g_sums[g * HDIM + i] * inv;
    __syncthreads();
    float a = fc1b[tid];
    for (int i = 0; i < HDIM; i++) a += ge[i] * fc1w[i * 64 + tid];
    h1[tid] = fmaxf(a, 0.f);
    __syncthreads();
    if (tid < 10) {
        float o = fc2b[tid];
        for (int j = 0; j < 64; j++) o += h1[j] * fc2w[j * 10 + tid];
        out[g * 10 + tid] = o;
    }
}

// ---------------------------------------------------------------------------

extern "C" void kernel_launch(void* const* d_in, const int* in_sizes, int n_in,
                              void* d_out, int out_size) {
    const float* x      = (const float*)d_in[0];
    const int*   eidx   = (const int*)  d_in[1];
    const int*   batch  = (const int*)  d_in[2];
    const float* W_in   = (const float*)d_in[3];
    const float* b_in   = (const float*)d_in[4];
    const float* Ws     = (const float*)d_in[5];
    const float* bs     = (const float*)d_in[6];
    const float* gammas = (const float*)d_in[7];
    const float* betas  = (const float*)d_in[8];
    const float* rmeans = (const float*)d_in[9];
    const float* rvars  = (const float*)d_in[10];
    const float* fc1w   = (const float*)d_in[11];
    const float* fc1b   = (const float*)d_in[12];
    const float* fc2w   = (const float*)d_in[13];
    const float* fc2b   = (const float*)d_in[14];
    float* out = (float*)d_out;

    int N = in_sizes[2];
    int E = in_sizes[1] / 2;
    const int* src = eidx;
    const int* dst = eidx + E;

    const int TB = 256;
    k_zero_deg<<<(N + TB - 1) / TB, TB>>>(N);
    k_hist<<<(E + TB - 1) / TB, TB>>>(dst, E);
    k_dinv<<<(N + TB - 1) / TB, TB>>>(N);
    int nb = (N + 1023) / 1024;
    k_scan1<<<nb, 1024>>>(N);
    k_scan2<<<1, 128>>>(nb);
    k_scan3<<<nb, 1024>>>(N);
    k_scatter<<<(E + TB - 1) / TB, TB>>>(src, dst, E);

    int gblk = (N + 127) / 128;
    k_gemm<0><<<gblk, 256>>>(x, W_in, b_in, N);
    for (int l = 0; l < LAYERS; l++) {
        k_gemm<1><<<gblk, 256>>>(nullptr, Ws + (size_t)l * HDIM * HDIM, nullptr, N);
        int aggBlocks = (N * 32 + TB - 1) / TB;
        k_agg<<<aggBlocks, TB>>>(bs + l * HDIM, gammas + l * HDIM, betas + l * HDIM,
                                 rmeans + l * HDIM, rvars + l * HDIM, N, E);
    }

    k_zero_pool<<<(GMAX * HDIM + TB - 1) / TB, TB>>>();
    k_pool<<<(N * 32 + TB - 1) / TB, TB>>>(batch, N);
    int G = out_size / 10;
    k_head<<<G, 64>>>(fc1w, fc1b, fc2w, fc2b, out);
}

// round 4
// speedup vs baseline: 1.0913x; 1.0913x over previous
#include <cuda_runtime.h>

// ---------------------------------------------------------------------------
// BaselineGNN: 4-layer GCN inference.
//   1. degree histogram -> dinv = rsqrt(deg+1)
//   2. CSR build by dst (scan + scatter, precomputed edge weight)
//   3. h = relu(x @ W_in + b_in)           [FFMA2-packed fp32 GEMM]
//   4. 4x { hw = h @ Ws[l];  h = relu(BN(gather_csr(hw) + hw*selfw + b)) }
//   5. segmented mean-pool (batch sorted) fused with 2-layer MLP head
// ---------------------------------------------------------------------------

namespace {
constexpr int NMAX  = 100000;
constexpr int EMAX  = 1600000;
constexpr int HDIM  = 128;
constexpr int GMAX  = 256;
constexpr int LAYERS = 4;
constexpr float EPSV = 1e-5f;
}

__device__ float g_h [NMAX * HDIM];
__device__ float g_hw[NMAX * HDIM];
__device__ int   g_degc[NMAX];
__device__ float g_dinv[NMAX];
__device__ int   g_off[NMAX];
__device__ int   g_cur[NMAX];
__device__ int   g_bsums[128];
__device__ int   g_csr_src[EMAX];
__device__ float g_csr_w[EMAX];
__device__ int   g_gstart[GMAX + 1];

// ---------------------------------------------------------------------------

__global__ void k_zero_deg(int n) {
    int i = blockIdx.x * blockDim.x + threadIdx.x;
    if (i < n) g_degc[i] = 0;
}

__global__ void k_hist(const int* __restrict__ dst, int e) {
    int i = blockIdx.x * blockDim.x + threadIdx.x;
    if (i < e) atomicAdd(&g_degc[dst[i]], 1);
}

__global__ void k_dinv(int n) {
    int i = blockIdx.x * blockDim.x + threadIdx.x;
    if (i < n) g_dinv[i] = rsqrtf((float)(g_degc[i] + 1));
}

__global__ void k_scan1(int n) {
    __shared__ int tmp[1024];
    int gid = blockIdx.x * 1024 + threadIdx.x;
    int v = (gid < n) ? g_degc[gid] : 0;
    tmp[threadIdx.x] = v;
    __syncthreads();
    for (int d = 1; d < 1024; d <<= 1) {
        int t = (threadIdx.x >= d) ? tmp[threadIdx.x - d] : 0;
        __syncthreads();
        tmp[threadIdx.x] += t;
        __syncthreads();
    }
    if (gid < n) g_off[gid] = tmp[threadIdx.x] - v;   // exclusive
    if (threadIdx.x == 1023) g_bsums[blockIdx.x] = tmp[1023];
}

__global__ void k_scan2(int nb) {
    __shared__ int s[128];
    int tid = threadIdx.x;
    if (tid < nb) s[tid] = g_bsums[tid];
    __syncthreads();
    if (tid == 0) {
        int run = 0;
        for (int i = 0; i < nb; i++) { int t = s[i]; s[i] = run; run += t; }
    }
    __syncthreads();
    if (tid < nb) g_bsums[tid] = s[tid];
}

__global__ void k_scan3(int n) {
    int gid = blockIdx.x * 1024 + threadIdx.x;
    if (gid < n) {
        int v = g_off[gid] + g_bsums[blockIdx.x];
        g_off[gid] = v;
        g_cur[gid] = v;
    }
}

__global__ void k_scatter(const int* __restrict__ src, const int* __restrict__ dst, int e) {
    int i = blockIdx.x * blockDim.x + threadIdx.x;
    if (i < e) {
        int d = dst[i], s = src[i];
        int p = atomicAdd(&g_cur[d], 1);
        g_csr_src[p] = s;
        g_csr_w[p]   = g_dinv[s] * g_dinv[d];
    }
}

// graph boundaries from sorted batch: g_gstart[g] = first node of graph g
__global__ void k_gbound(const int* __restrict__ batch, int n, int G) {
    int i = blockIdx.x * blockDim.x + threadIdx.x;
    if (i >= n) return;
    int bi = batch[i];
    int bp = (i == 0) ? -1 : batch[i - 1];
    for (int g = bp + 1; g <= bi; g++) g_gstart[g] = i;
    if (i == n - 1)
        for (int g = bi + 1; g <= G; g++) g_gstart[g] = n;
}

// ---------------------------------------------------------------------------
// fp32 SGEMM with packed f32x2 FMA:  C[M,128] = A[M,128] @ B[128,128]
// BM=128, BN=128, BK=16, 256 threads, 8x8 per thread.
// Accumulators packed pairwise along N -> 32 fma.rn.f32x2 per kk.
// MODE 0: A = x param, C = g_h, bias+relu.   MODE 1: A = g_h, C = g_hw.
// ---------------------------------------------------------------------------
template <int MODE>
__global__ void __launch_bounds__(256, 2)
k_gemm(const float* __restrict__ Ap, const float* __restrict__ B,
       const float* __restrict__ bias, int M) {
    const float* A = (MODE == 0) ? Ap : g_h;
    float*       C = (MODE == 0) ? g_h : g_hw;
    __shared__ float As[16][132];   // [k][m], padded
    __shared__ float Bs[16][128];   // [k][n]
    int tid = threadIdx.x;
    int tx = tid & 15;
    int ty = tid >> 4;
    int row0 = blockIdx.x * 128;

    unsigned long long acc2[8][4];  // acc2[i][j] = (C[i][2j], C[i][2j+1])
#pragma unroll
    for (int i = 0; i < 8; i++)
#pragma unroll
        for (int j = 0; j < 4; j++) acc2[i][j] = 0ULL;

    for (int k0 = 0; k0 < 128; k0 += 16) {
#pragma unroll
        for (int t = 0; t < 2; t++) {
            int idx = tid * 2 + t;
            int r  = idx >> 2;
            int kk = (idx & 3) * 4;
            float4 v = make_float4(0.f, 0.f, 0.f, 0.f);
            if (row0 + r < M)
                v = *(const float4*)&A[(size_t)(row0 + r) * 128 + k0 + kk];
            As[kk + 0][r] = v.x; As[kk + 1][r] = v.y;
            As[kk + 2][r] = v.z; As[kk + 3][r] = v.w;
        }
#pragma unroll
        for (int t = 0; t < 2; t++) {
            int idx = tid * 2 + t;
            int kk = idx >> 5;
            int c  = (idx & 31) * 4;
            *(float4*)&Bs[kk][c] = *(const float4*)&B[(size_t)(k0 + kk) * 128 + c];
        }
        __syncthreads();
#pragma unroll
        for (int kk = 0; kk < 16; kk++) {
            float a[8];
            *(float4*)&a[0] = *(const float4*)&As[kk][ty * 8];
            *(float4*)&a[4] = *(const float4*)&As[kk][ty * 8 + 4];
            float4 bq0 = *(const float4*)&Bs[kk][tx * 8];
            float4 bq1 = *(const float4*)&Bs[kk][tx * 8 + 4];
            unsigned long long bp[4];
            bp[0] = ((const unsigned long long*)&bq0)[0];
            bp[1] = ((const unsigned long long*)&bq0)[1];
            bp[2] = ((const unsigned long long*)&bq1)[0];
            bp[3] = ((const unsigned long long*)&bq1)[1];
#pragma unroll
            for (int i = 0; i < 8; i++) {
                unsigned long long ap;
                asm("mov.b64 %0, {%1, %1};" : "=l"(ap) : "f"(a[i]));
#pragma unroll
                for (int j = 0; j < 4; j++) {
                    asm("fma.rn.f32x2 %0, %1, %2, %0;"
                        : "+l"(acc2[i][j]) : "l"(ap), "l"(bp[j]));
                }
            }
        }
        __syncthreads();
    }
#pragma unroll
    for (int i = 0; i < 8; i++) {
        int r = row0 + ty * 8 + i;
        if (r < M) {
#pragma unroll
            for (int jj = 0; jj < 2; jj++) {        // two float4 stores
                int c = tx * 8 + jj * 4;
                float4 v;
                asm("mov.b64 {%0, %1}, %2;" : "=f"(v.x), "=f"(v.y) : "l"(acc2[i][jj * 2]));
                asm("mov.b64 {%0, %1}, %2;" : "=f"(v.z), "=f"(v.w) : "l"(acc2[i][jj * 2 + 1]));
                if (MODE == 0) {
                    v.x += bias[c];     v.y += bias[c + 1];
                    v.z += bias[c + 2]; v.w += bias[c + 3];
                    v.x = fmaxf(v.x, 0.f); v.y = fmaxf(v.y, 0.f);
                    v.z = fmaxf(v.z, 0.f); v.w = fmaxf(v.w, 0.f);
                }
                *(float4*)&C[(size_t)r * 128 + c] = v;
            }
        }
    }
}

// ---------------------------------------------------------------------------
// CSR gather + self-loop + bias + BN(eval) + relu.  One warp per node; each
// lane owns 4 consecutive features.  Edge loop unrolled x4 for MLP.
// ---------------------------------------------------------------------------
__global__ void k_agg(const float* __restrict__ bias,
                      const float* __restrict__ gamma,
                      const float* __restrict__ beta,
                      const float* __restrict__ rmean,
                      const float* __restrict__ rvar,
                      int n, int e) {
    int w    = (blockIdx.x * blockDim.x + threadIdx.x) >> 5;
    int lane = threadIdx.x & 31;
    if (w >= n) return;
    int f = lane * 4;
    const float* hw = g_hw;

    float dv = g_dinv[w];
    float ws = dv * dv;
    float4 hv = *(const float4*)(hw + (size_t)w * HDIM + f);
    float ax = hv.x * ws, ay = hv.y * ws, az = hv.z * ws, aw = hv.w * ws;
    float bx = 0.f, by = 0.f, bz = 0.f, bw = 0.f;

    int j0 = g_off[w];
    int j1 = (w + 1 < n) ? g_off[w + 1] : e;
    int j = j0;
    for (; j + 4 <= j1; j += 4) {
        int s0 = g_csr_src[j];     float w0 = g_csr_w[j];
        int s1 = g_csr_src[j + 1]; float w1 = g_csr_w[j + 1];
        int s2 = g_csr_src[j + 2]; float w2 = g_csr_w[j + 2];
        int s3 = g_csr_src[j + 3]; float w3 = g_csr_w[j + 3];
        float4 v0 = *(const float4*)(hw + (size_t)s0 * HDIM + f);
        float4 v1 = *(const float4*)(hw + (size_t)s1 * HDIM + f);
        float4 v2 = *(const float4*)(hw + (size_t)s2 * HDIM + f);
        float4 v3 = *(const float4*)(hw + (size_t)s3 * HDIM + f);
        ax += v0.x * w0; ay += v0.y * w0; az += v0.z * w0; aw += v0.w * w0;
        bx += v1.x * w1; by += v1.y * w1; bz += v1.z * w1; bw += v1.w * w1;
        ax += v2.x * w2; ay += v2.y * w2; az += v2.z * w2; aw += v2.w * w2;
        bx += v3.x * w3; by += v3.y * w3; bz += v3.z * w3; bw += v3.w * w3;
    }
    for (; j < j1; j++) {
        int   s  = g_csr_src[j];
        float wt = g_csr_w[j];
        float4 v = *(const float4*)(hw + (size_t)s * HDIM + f);
        ax += v.x * wt; ay += v.y * wt; az += v.z * wt; aw += v.w * wt;
    }
    ax += bx; ay += by; az += bz; aw += bw;

    float4 bb = *(const float4*)(bias  + f);
    float4 gm = *(const float4*)(gamma + f);
    float4 bt = *(const float4*)(beta  + f);
    float4 rm = *(const float4*)(rmean + f);
    float4 rv = *(const float4*)(rvar  + f);
    float4 o;
    o.x = fmaxf((ax + bb.x - rm.x) * rsqrtf(rv.x + EPSV) * gm.x + bt.x, 0.f);
    o.y = fmaxf((ay + bb.y - rm.y) * rsqrtf(rv.y + EPSV) * gm.y + bt.y, 0.f);
    o.z = fmaxf((az + bb.z - rm.z) * rsqrtf(rv.z + EPSV) * gm.z + bt.z, 0.f);
    o.w = fmaxf((aw + bb.w - rm.w) * rsqrtf(rv.w + EPSV) * gm.w + bt.w, 0.f);
    *(float4*)(g_h + (size_t)w * HDIM + f) = o;
}

// ---------------------------------------------------------------------------
// Fused segmented mean-pool + MLP head.  One block (256 threads) per graph.
// Deterministic (no atomics): batch is sorted, boundaries precomputed.
// ---------------------------------------------------------------------------
__global__ void k_poolhead(const float* __restrict__ fc1w, const float* __restrict__ fc1b,
                           const float* __restrict__ fc2w, const float* __restrict__ fc2b,
                           float* __restrict__ out) {
    int g   = blockIdx.x;
    int tid = threadIdx.x;          // 256
    int t    = tid & 127;           // feature
    int half = tid >> 7;            // 0/1
    __shared__ float ssum[HDIM];
    __shared__ float ge[HDIM];
    __shared__ float h1[64];

    int s0 = g_gstart[g];
    int s1 = g_gstart[g + 1];
    float acc = 0.f;
#pragma unroll 4
    for (int r = s0 + half; r < s1; r += 2)
        acc += g_h[(size_t)r * HDIM + t];
    if (half == 1) ssum[t] = acc;
    __syncthreads();
    if (half == 0) {
        float cnt = fmaxf((float)(s1 - s0), 1.f);
        ge[t] = (acc + ssum[t]) / cnt;
    }
    __syncthreads();

    if (tid < 64) {
        float a = fc1b[tid];
#pragma unroll
        for (int i = 0; i < HDIM; i++) a += ge[i] * fc1w[i * 64 + tid];
        h1[tid] = fmaxf(a, 0.f);
    }
    __syncthreads();
    if (tid < 10) {
        float o = fc2b[tid];
#pragma unroll
        for (int jq = 0; jq < 64; jq++) o += h1[jq] * fc2w[jq * 10 + tid];
        out[g * 10 + tid] = o;
    }
}

// ---------------------------------------------------------------------------

extern "C" void kernel_launch(void* const* d_in, const int* in_sizes, int n_in,
                              void* d_out, int out_size) {
    const float* x      = (const float*)d_in[0];
    const int*   eidx   = (const int*)  d_in[1];
    const int*   batch  = (const int*)  d_in[2];
    const float* W_in   = (const float*)d_in[3];
    const float* b_in   = (const float*)d_in[4];
    const float* Ws     = (const float*)d_in[5];
    const float* bs     = (const float*)d_in[6];
    const float* gammas = (const float*)d_in[7];
    const float* betas  = (const float*)d_in[8];
    const float* rmeans = (const float*)d_in[9];
    const float* rvars  = (const float*)d_in[10];
    const float* fc1w   = (const float*)d_in[11];
    const float* fc1b   = (const float*)d_in[12];
    const float* fc2w   = (const float*)d_in[13];
    const float* fc2b   = (const float*)d_in[14];
    float* out = (float*)d_out;

    int N = in_sizes[2];
    int E = in_sizes[1] / 2;
    int G = out_size / 10;
    const int* src = eidx;
    const int* dst = eidx + E;

    const int TB = 256;
    k_zero_deg<<<(N + TB - 1) / TB, TB>>>(N);
    k_hist<<<(E + TB - 1) / TB, TB>>>(dst, E);
    k_dinv<<<(N + TB - 1) / TB, TB>>>(N);
    int nb = (N + 1023) / 1024;
    k_scan1<<<nb, 1024>>>(N);
    k_scan2<<<1, 128>>>(nb);
    k_scan3<<<nb, 1024>>>(N);
    k_scatter<<<(E + TB - 1) / TB, TB>>>(src, dst, E);
    k_gbound<<<(N + TB - 1) / TB, TB>>>(batch, N, G);

    int gblk = (N + 127) / 128;
    k_gemm<0><<<gblk, 256>>>(x, W_in, b_in, N);
    for (int l = 0; l < LAYERS; l++) {
        k_gemm<1><<<gblk, 256>>>(nullptr, Ws + (size_t)l * HDIM * HDIM, nullptr, N);
        int aggBlocks = (N * 32 + TB - 1) / TB;
        k_agg<<<aggBlocks, TB>>>(bs + l * HDIM, gammas + l * HDIM, betas + l * HDIM,
                                 rmeans + l * HDIM, rvars + l * HDIM, N, E);
    }

    k_poolhead<<<G, 256>>>(fc1w, fc1b, fc2w, fc2b, out);
}

// round 5
// speedup vs baseline: 2.0350x; 1.8648x over previous
#include <cuda_runtime.h>
#include <cuda_bf16.h>
#include <cstdint>

// ---------------------------------------------------------------------------
// BaselineGNN: 4-layer GCN inference.
//   CSR build (unchanged) ->
//   bf16 tensor-core GEMMs (split-weight hi+lo for fp32-grade weight accuracy)
//   bf16 CSR gather + BN + relu (fp32 accumulate)
//   deterministic segmented mean-pool + MLP head
// ---------------------------------------------------------------------------

namespace {
constexpr int NMAX  = 100000;
constexpr int EMAX  = 1600000;
constexpr int HDIM  = 128;
constexpr int GMAX  = 256;
constexpr int LAYERS = 4;
constexpr float EPSV = 1e-5f;
}

__device__ __nv_bfloat16 g_hbf [NMAX * HDIM];   // h  (GEMM input / agg output)
__device__ __nv_bfloat16 g_hwbf[NMAX * HDIM];   // hw (GEMM output / agg input)
__device__ float g_h [NMAX * HDIM];             // fp32 h for final pool
__device__ __nv_bfloat16 g_wbf_hi[5 * HDIM * HDIM];
__device__ __nv_bfloat16 g_wbf_lo[5 * HDIM * HDIM];
__device__ int   g_degc[NMAX];
__device__ float g_dinv[NMAX];
__device__ int   g_off[NMAX];
__device__ int   g_cur[NMAX];
__device__ int   g_bsums[128];
__device__ int   g_csr_src[EMAX];
__device__ float g_csr_w[EMAX];
__device__ int   g_gstart[GMAX + 1];

// ---------------------------------------------------------------------------

__global__ void k_zero_deg(int n) {
    int i = blockIdx.x * blockDim.x + threadIdx.x;
    if (i < n) g_degc[i] = 0;
}

__global__ void k_hist(const int* __restrict__ dst, int e) {
    int i = blockIdx.x * blockDim.x + threadIdx.x;
    if (i < e) atomicAdd(&g_degc[dst[i]], 1);
}

__global__ void k_dinv(int n) {
    int i = blockIdx.x * blockDim.x + threadIdx.x;
    if (i < n) g_dinv[i] = rsqrtf((float)(g_degc[i] + 1));
}

__global__ void k_scan1(int n) {
    __shared__ int tmp[1024];
    int gid = blockIdx.x * 1024 + threadIdx.x;
    int v = (gid < n) ? g_degc[gid] : 0;
    tmp[threadIdx.x] = v;
    __syncthreads();
    for (int d = 1; d < 1024; d <<= 1) {
        int t = (threadIdx.x >= d) ? tmp[threadIdx.x - d] : 0;
        __syncthreads();
        tmp[threadIdx.x] += t;
        __syncthreads();
    }
    if (gid < n) g_off[gid] = tmp[threadIdx.x] - v;   // exclusive
    if (threadIdx.x == 1023) g_bsums[blockIdx.x] = tmp[1023];
}

__global__ void k_scan2(int nb) {
    __shared__ int s[128];
    int tid = threadIdx.x;
    if (tid < nb) s[tid] = g_bsums[tid];
    __syncthreads();
    if (tid == 0) {
        int run = 0;
        for (int i = 0; i < nb; i++) { int t = s[i]; s[i] = run; run += t; }
    }
    __syncthreads();
    if (tid < nb) g_bsums[tid] = s[tid];
}

__global__ void k_scan3(int n) {
    int gid = blockIdx.x * 1024 + threadIdx.x;
    if (gid < n) {
        int v = g_off[gid] + g_bsums[blockIdx.x];
        g_off[gid] = v;
        g_cur[gid] = v;
    }
}

__global__ void k_scatter(const int* __restrict__ src, const int* __restrict__ dst, int e) {
    int i = blockIdx.x * blockDim.x + threadIdx.x;
    if (i < e) {
        int d = dst[i], s = src[i];
        int p = atomicAdd(&g_cur[d], 1);
        g_csr_src[p] = s;
        g_csr_w[p]   = g_dinv[s] * g_dinv[d];
    }
}

__global__ void k_gbound(const int* __restrict__ batch, int n, int G) {
    int i = blockIdx.x * blockDim.x + threadIdx.x;
    if (i >= n) return;
    int bi = batch[i];
    int bp = (i == 0) ? -1 : batch[i - 1];
    for (int g = bp + 1; g <= bi; g++) g_gstart[g] = i;
    if (i == n - 1)
        for (int g = bi + 1; g <= G; g++) g_gstart[g] = n;
}

// Convert W_in (16384) + Ws (4*16384) to split bf16 hi/lo.
__global__ void k_cvtW(const float* __restrict__ W_in, const float* __restrict__ Ws) {
    int i = blockIdx.x * blockDim.x + threadIdx.x;
    if (i >= 5 * HDIM * HDIM) return;
    float w = (i < HDIM * HDIM) ? W_in[i] : Ws[i - HDIM * HDIM];
    __nv_bfloat16 hi = __float2bfloat16_rn(w);
    g_wbf_hi[i] = hi;
    g_wbf_lo[i] = __float2bfloat16_rn(w - __bfloat162float(hi));
}

// ---------------------------------------------------------------------------
// Tensor-core GEMM: C[M,128] = A[M,128] @ (W_hi + W_lo)[128,128]
// BM=128, full K in two 64-wide stages.  8 warps: wm=wid&3 (32 rows),
// wn=wid>>2 (64 cols).  mma.m16n8k16 bf16 -> fp32.
// MODE 0: A = x (fp32, converted), out = g_hbf, +bias+relu.
// MODE 1: A = g_hbf,               out = g_hwbf.
// ---------------------------------------------------------------------------

__device__ __forceinline__ void ldsm_x4(uint32_t* r, uint32_t addr) {
    asm volatile("ldmatrix.sync.aligned.m8n8.x4.shared.b16 {%0,%1,%2,%3}, [%4];"
        : "=r"(r[0]), "=r"(r[1]), "=r"(r[2]), "=r"(r[3]) : "r"(addr));
}
__device__ __forceinline__ void ldsm_x4_t(uint32_t* r, uint32_t addr) {
    asm volatile("ldmatrix.sync.aligned.m8n8.x4.trans.shared.b16 {%0,%1,%2,%3}, [%4];"
        : "=r"(r[0]), "=r"(r[1]), "=r"(r[2]), "=r"(r[3]) : "r"(addr));
}
__device__ __forceinline__ void mma_bf16(float* c, const uint32_t* a, uint32_t b0, uint32_t b1) {
    asm volatile("mma.sync.aligned.m16n8k16.row.col.f32.bf16.bf16.f32 "
        "{%0,%1,%2,%3}, {%4,%5,%6,%7}, {%8,%9}, {%0,%1,%2,%3};"
        : "+f"(c[0]), "+f"(c[1]), "+f"(c[2]), "+f"(c[3])
        : "r"(a[0]), "r"(a[1]), "r"(a[2]), "r"(a[3]), "r"(b0), "r"(b1));
}

template <int MODE>
__global__ void __launch_bounds__(256)
k_gemm_tc(const float* __restrict__ Afp, int loff,
          const float* __restrict__ bias, int M) {
    __shared__ __nv_bfloat16 As [128 * 64];   // 16KB, swizzled: a16 = r*8  + (c ^ (r&7))
    __shared__ __nv_bfloat16 Bhs[64 * 128];   // 16KB, swizzled: a16 = k*16 + ((c&8)|((c&7)^(k&7)))
    __shared__ __nv_bfloat16 Bls[64 * 128];   // 16KB
    const __nv_bfloat16* Whi = g_wbf_hi + loff;
    const __nv_bfloat16* Wlo = g_wbf_lo + loff;

    int tid  = threadIdx.x;
    int lane = tid & 31, wid = tid >> 5;
    int wm = wid & 3, wn = wid >> 2;
    int row0 = blockIdx.x * 128;

    uint32_t asb = (uint32_t)__cvta_generic_to_shared(As);
    uint32_t bhb = (uint32_t)__cvta_generic_to_shared(Bhs);
    uint32_t blb = (uint32_t)__cvta_generic_to_shared(Bls);

    float acc[2][8][4];
#pragma unroll
    for (int mi = 0; mi < 2; mi++)
#pragma unroll
        for (int nj = 0; nj < 8; nj++)
#pragma unroll
            for (int q = 0; q < 4; q++) acc[mi][nj][q] = 0.f;

    for (int s = 0; s < 2; s++) {
        int k0 = s * 64;
        if (s) __syncthreads();
        // ---- load A stage: 128 rows x 64 k (chunks of 8 bf16 = 16B) ----
#pragma unroll
        for (int i = 0; i < 4; i++) {
            int idx = tid + 256 * i;
            int r = idx >> 3, c = idx & 7;
            int gr = row0 + r;
            uint4 u = make_uint4(0u, 0u, 0u, 0u);
            if (gr < M) {
                if (MODE == 0) {
                    const float4* p = (const float4*)(Afp + (size_t)gr * 128 + k0 + c * 8);
                    float4 f0 = p[0], f1 = p[1];
                    __nv_bfloat162 h0 = __floats2bfloat162_rn(f0.x, f0.y);
                    __nv_bfloat162 h1 = __floats2bfloat162_rn(f0.z, f0.w);
                    __nv_bfloat162 h2 = __floats2bfloat162_rn(f1.x, f1.y);
                    __nv_bfloat162 h3 = __floats2bfloat162_rn(f1.z, f1.w);
                    u.x = *(uint32_t*)&h0; u.y = *(uint32_t*)&h1;
                    u.z = *(uint32_t*)&h2; u.w = *(uint32_t*)&h3;
                } else {
                    u = *(const uint4*)(g_hbf + (size_t)gr * 128 + k0 + c * 8);
                }
            }
            *(uint4*)(As + (size_t)((r << 3) + (c ^ (r & 7))) * 8) = u;
        }
        // ---- load B stage: 64 k-rows x 128 n (16 chunks per row) ----
#pragma unroll
        for (int i = 0; i < 4; i++) {
            int idx = tid + 256 * i;
            int k = idx >> 4, c = idx & 15;
            int sw = (c & 8) | ((c & 7) ^ (k & 7));
            *(uint4*)(Bhs + (size_t)(k * 16 + sw) * 8) =
                *(const uint4*)(Whi + (size_t)(k0 + k) * 128 + c * 8);
            *(uint4*)(Bls + (size_t)(k * 16 + sw) * 8) =
                *(const uint4*)(Wlo + (size_t)(k0 + k) * 128 + c * 8);
        }
        __syncthreads();
        // ---- compute: 4 k-steps of 16 ----
#pragma unroll
        for (int ks = 0; ks < 4; ks++) {
            uint32_t a[2][4];
#pragma unroll
            for (int mi = 0; mi < 2; mi++) {
                int r  = wm * 32 + mi * 16 + (lane & 15);
                int ch = ks * 2 + (lane >> 4);
                ldsm_x4(a[mi], asb + (uint32_t)((r << 3) + (ch ^ (r & 7))) * 16);
            }
#pragma unroll
            for (int nj = 0; nj < 4; nj++) {        // 4 n-pairs of 16 cols
                int k  = ks * 16 + (lane & 15);
                int ch = wn * 8 + nj * 2 + (lane >> 4);
                int sw = (ch & 8) | ((ch & 7) ^ (k & 7));
                uint32_t bh[4], bl[4];
                ldsm_x4_t(bh, bhb + (uint32_t)(k * 16 + sw) * 16);
                ldsm_x4_t(bl, blb + (uint32_t)(k * 16 + sw) * 16);
#pragma unroll
                for (int mi = 0; mi < 2; mi++) {
                    mma_bf16(acc[mi][nj * 2],     a[mi], bh[0], bh[1]);
                    mma_bf16(acc[mi][nj * 2 + 1], a[mi], bh[2], bh[3]);
                    mma_bf16(acc[mi][nj * 2],     a[mi], bl[0], bl[1]);
                    mma_bf16(acc[mi][nj * 2 + 1], a[mi], bl[2], bl[3]);
                }
            }
        }
    }
    // ---- epilogue ----
    int gid = lane >> 2, tig = lane & 3;
    __nv_bfloat16* Out = (MODE == 0) ? g_hbf : g_hwbf;
#pragma unroll
    for (int mi = 0; mi < 2; mi++) {
#pragma unroll
        for (int nj = 0; nj < 8; nj++) {
            int col = wn * 64 + nj * 8 + tig * 2;
            float v0 = acc[mi][nj][0], v1 = acc[mi][nj][1];
            float v2 = acc[mi][nj][2], v3 = acc[mi][nj][3];
            if (MODE == 0) {
                float b0 = bias[col], b1 = bias[col + 1];
                v0 = fmaxf(v0 + b0, 0.f); v1 = fmaxf(v1 + b1, 0.f);
                v2 = fmaxf(v2 + b0, 0.f); v3 = fmaxf(v3 + b1, 0.f);
            }
            int r0 = row0 + wm * 32 + mi * 16 + gid;
            int r1 = r0 + 8;
            if (r0 < M) {
                __nv_bfloat162 p = __floats2bfloat162_rn(v0, v1);
                *(uint32_t*)(Out + (size_t)r0 * 128 + col) = *(uint32_t*)&p;
            }
            if (r1 < M) {
                __nv_bfloat162 p = __floats2bfloat162_rn(v2, v3);
                *(uint32_t*)(Out + (size_t)r1 * 128 + col) = *(uint32_t*)&p;
            }
        }
    }
}

// ---------------------------------------------------------------------------
// bf16 CSR gather + self-loop + bias + BN + relu (fp32 accumulate).
// One warp per node; lane owns 4 features (8B uint2 per edge).
// Writes g_hbf (next GEMM) and g_h (fp32, for final pool).
// ---------------------------------------------------------------------------
__global__ void k_agg(const float* __restrict__ bias,
                      const float* __restrict__ gamma,
                      const float* __restrict__ beta,
                      const float* __restrict__ rmean,
                      const float* __restrict__ rvar,
                      int n, int e) {
    int w    = (blockIdx.x * blockDim.x + threadIdx.x) >> 5;
    int lane = threadIdx.x & 31;
    if (w >= n) return;
    int f = lane * 4;
    const __nv_bfloat16* hw = g_hwbf;

    float dv = g_dinv[w];
    float ws = dv * dv;
    uint2 us = *(const uint2*)(hw + (size_t)w * HDIM + f);
    float2 s0 = __bfloat1622float2(*(__nv_bfloat162*)&us.x);
    float2 s1 = __bfloat1622float2(*(__nv_bfloat162*)&us.y);
    float ax = s0.x * ws, ay = s0.y * ws, az = s1.x * ws, aw = s1.y * ws;
    float bx = 0.f, by = 0.f, bz = 0.f, bw = 0.f;

    int j0 = g_off[w];
    int j1 = (w + 1 < n) ? g_off[w + 1] : e;
    int j = j0;
    for (; j + 4 <= j1; j += 4) {
        int n0 = g_csr_src[j];     float w0 = g_csr_w[j];
        int n1 = g_csr_src[j + 1]; float w1 = g_csr_w[j + 1];
        int n2 = g_csr_src[j + 2]; float w2 = g_csr_w[j + 2];
        int n3 = g_csr_src[j + 3]; float w3 = g_csr_w[j + 3];
        uint2 u0 = *(const uint2*)(hw + (size_t)n0 * HDIM + f);
        uint2 u1 = *(const uint2*)(hw + (size_t)n1 * HDIM + f);
        uint2 u2 = *(const uint2*)(hw + (size_t)n2 * HDIM + f);
        uint2 u3 = *(const uint2*)(hw + (size_t)n3 * HDIM + f);
        float2 a0 = __bfloat1622float2(*(__nv_bfloat162*)&u0.x);
        float2 a1 = __bfloat1622float2(*(__nv_bfloat162*)&u0.y);
        ax += a0.x * w0; ay += a0.y * w0; az += a1.x * w0; aw += a1.y * w0;
        float2 c0 = __bfloat1622float2(*(__nv_bfloat162*)&u1.x);
        float2 c1 = __bfloat1622float2(*(__nv_bfloat162*)&u1.y);
        bx += c0.x * w1; by += c0.y * w1; bz += c1.x * w1; bw += c1.y * w1;
        float2 d0 = __bfloat1622float2(*(__nv_bfloat162*)&u2.x);
        float2 d1 = __bfloat1622float2(*(__nv_bfloat162*)&u2.y);
        ax += d0.x * w2; ay += d0.y * w2; az += d1.x * w2; aw += d1.y * w2;
        float2 e0 = __bfloat1622float2(*(__nv_bfloat162*)&u3.x);
        float2 e1 = __bfloat1622float2(*(__nv_bfloat162*)&u3.y);
        bx += e0.x * w3; by += e0.y * w3; bz += e1.x * w3; bw += e1.y * w3;
    }
    for (; j < j1; j++) {
        int   sj = g_csr_src[j];
        float wt = g_csr_w[j];
        uint2 u = *(const uint2*)(hw + (size_t)sj * HDIM + f);
        float2 a0 = __bfloat1622float2(*(__nv_bfloat162*)&u.x);
        float2 a1 = __bfloat1622float2(*(__nv_bfloat162*)&u.y);
        ax += a0.x * wt; ay += a0.y * wt; az += a1.x * wt; aw += a1.y * wt;
    }
    ax += bx; ay += by; az += bz; aw += bw;

    float4 bb = *(const float4*)(bias  + f);
    float4 gm = *(const float4*)(gamma + f);
    float4 bt = *(const float4*)(beta  + f);
    float4 rm = *(const float4*)(rmean + f);
    float4 rv = *(const float4*)(rvar  + f);
    float4 o;
    o.x = fmaxf((ax + bb.x - rm.x) * rsqrtf(rv.x + EPSV) * gm.x + bt.x, 0.f);
    o.y = fmaxf((ay + bb.y - rm.y) * rsqrtf(rv.y + EPSV) * gm.y + bt.y, 0.f);
    o.z = fmaxf((az + bb.z - rm.z) * rsqrtf(rv.z + EPSV) * gm.z + bt.z, 0.f);
    o.w = fmaxf((aw + bb.w - rm.w) * rsqrtf(rv.w + EPSV) * gm.w + bt.w, 0.f);
    *(float4*)(g_h + (size_t)w * HDIM + f) = o;
    __nv_bfloat162 q0 = __floats2bfloat162_rn(o.x, o.y);
    __nv_bfloat162 q1 = __floats2bfloat162_rn(o.z, o.w);
    uint2 qo; qo.x = *(uint32_t*)&q0; qo.y = *(uint32_t*)&q1;
    *(uint2*)(g_hbf + (size_t)w * HDIM + f) = qo;
}

// ---------------------------------------------------------------------------
// Fused segmented mean-pool + MLP head (deterministic, no atomics).
// ---------------------------------------------------------------------------
__global__ void k_poolhead(const float* __restrict__ fc1w, const float* __restrict__ fc1b,
                           const float* __restrict__ fc2w, const float* __restrict__ fc2b,
                           float* __restrict__ out) {
    int g   = blockIdx.x;
    int tid = threadIdx.x;          // 256
    int t    = tid & 127;
    int half = tid >> 7;
    __shared__ float ssum[HDIM];
    __shared__ float ge[HDIM];
    __shared__ float h1[64];

    int s0 = g_gstart[g];
    int s1 = g_gstart[g + 1];
    float acc = 0.f;
#pragma unroll 4
    for (int r = s0 + half; r < s1; r += 2)
        acc += g_h[(size_t)r * HDIM + t];
    if (half == 1) ssum[t] = acc;
    __syncthreads();
    if (half == 0) {
        float cnt = fmaxf((float)(s1 - s0), 1.f);
        ge[t] = (acc + ssum[t]) / cnt;
    }
    __syncthreads();

    if (tid < 64) {
        float a = fc1b[tid];
#pragma unroll
        for (int i = 0; i < HDIM; i++) a += ge[i] * fc1w[i * 64 + tid];
        h1[tid] = fmaxf(a, 0.f);
    }
    __syncthreads();
    if (tid < 10) {
        float o = fc2b[tid];
#pragma unroll
        for (int jq = 0; jq < 64; jq++) o += h1[jq] * fc2w[jq * 10 + tid];
        out[g * 10 + tid] = o;
    }
}

// ---------------------------------------------------------------------------

extern "C" void kernel_launch(void* const* d_in, const int* in_sizes, int n_in,
                              void* d_out, int out_size) {
    const float* x      = (const float*)d_in[0];
    const int*   eidx   = (const int*)  d_in[1];
    const int*   batch  = (const int*)  d_in[2];
    const float* W_in   = (const float*)d_in[3];
    const float* b_in   = (const float*)d_in[4];
    const float* Ws     = (const float*)d_in[5];
    const float* bs     = (const float*)d_in[6];
    const float* gammas = (const float*)d_in[7];
    const float* betas  = (const float*)d_in[8];
    const float* rmeans = (const float*)d_in[9];
    const float* rvars  = (const float*)d_in[10];
    const float* fc1w   = (const float*)d_in[11];
    const float* fc1b   = (const float*)d_in[12];
    const float* fc2w   = (const float*)d_in[13];
    const float* fc2b   = (const float*)d_in[14];
    float* out = (float*)d_out;

    int N = in_sizes[2];
    int E = in_sizes[1] / 2;
    int G = out_size / 10;
    const int* src = eidx;
    const int* dst = eidx + E;

    const int TB = 256;
    k_zero_deg<<<(N + TB - 1) / TB, TB>>>(N);
    k_hist<<<(E + TB - 1) / TB, TB>>>(dst, E);
    k_dinv<<<(N + TB - 1) / TB, TB>>>(N);
    int nb = (N + 1023) / 1024;
    k_scan1<<<nb, 1024>>>(N);
    k_scan2<<<1, 128>>>(nb);
    k_scan3<<<nb, 1024>>>(N);
    k_scatter<<<(E + TB - 1) / TB, TB>>>(src, dst, E);
    k_gbound<<<(N + TB - 1) / TB, TB>>>(batch, N, G);
    k_cvtW<<<(5 * HDIM * HDIM + TB - 1) / TB, TB>>>(W_in, Ws);

    int gblk = (N + 127) / 128;
    k_gemm_tc<0><<<gblk, 256>>>(x, 0, b_in, N);
    for (int l = 0; l < LAYERS; l++) {
        k_gemm_tc<1><<<gblk, 256>>>(nullptr, (1 + l) * HDIM * HDIM, nullptr, N);
        int aggBlocks = (N * 32 + TB - 1) / TB;
        k_agg<<<aggBlocks, TB>>>(bs + l * HDIM, gammas + l * HDIM, betas + l * HDIM,
                                 rmeans + l * HDIM, rvars + l * HDIM, N, E);
    }

    k_poolhead<<<G, 256>>>(fc1w, fc1b, fc2w, fc2b, out);
}

// round 6
// speedup vs baseline: 2.1140x; 1.0388x over previous
#include <cuda_runtime.h>
#include <cuda_bf16.h>
#include <cstdint>

// ---------------------------------------------------------------------------
// BaselineGNN: 4-layer GCN inference.
//   CSR build -> bf16 tensor-core GEMMs (split-weight hi+lo) ->
//   bf16 CSR gather (lane-cooperative CSR fetch) + BN + relu ->
//   deterministic segmented mean-pool (bf16 input) + MLP head
// ---------------------------------------------------------------------------

namespace {
constexpr int NMAX  = 100000;
constexpr int EMAX  = 1600000;
constexpr int HDIM  = 128;
constexpr int GMAX  = 256;
constexpr int LAYERS = 4;
constexpr float EPSV = 1e-5f;
}

__device__ __nv_bfloat16 g_hbf [NMAX * HDIM];   // h  (GEMM input / agg output / pool input)
__device__ __nv_bfloat16 g_hwbf[NMAX * HDIM];   // hw (GEMM output / agg input)
__device__ __nv_bfloat16 g_wbf_hi[5 * HDIM * HDIM];
__device__ __nv_bfloat16 g_wbf_lo[5 * HDIM * HDIM];
__device__ int   g_degc[NMAX];
__device__ float g_dinv[NMAX];
__device__ int   g_off[NMAX];
__device__ int   g_cur[NMAX];
__device__ int   g_bsums[128];
__device__ int   g_csr_src[EMAX];
__device__ float g_csr_w[EMAX];
__device__ int   g_gstart[GMAX + 1];

// ---------------------------------------------------------------------------

__global__ void k_zero_deg(int n) {
    int i = blockIdx.x * blockDim.x + threadIdx.x;
    if (i < n) g_degc[i] = 0;
}

__global__ void k_hist(const int* __restrict__ dst, int e) {
    int i = blockIdx.x * blockDim.x + threadIdx.x;
    if (i < e) atomicAdd(&g_degc[dst[i]], 1);
}

// scan1 also produces dinv = rsqrt(deg+1)
__global__ void k_scan1(int n) {
    __shared__ int tmp[1024];
    int gid = blockIdx.x * 1024 + threadIdx.x;
    int v = (gid < n) ? g_degc[gid] : 0;
    if (gid < n) g_dinv[gid] = rsqrtf((float)(v + 1));
    tmp[threadIdx.x] = v;
    __syncthreads();
    for (int d = 1; d < 1024; d <<= 1) {
        int t = (threadIdx.x >= d) ? tmp[threadIdx.x - d] : 0;
        __syncthreads();
        tmp[threadIdx.x] += t;
        __syncthreads();
    }
    if (gid < n) g_off[gid] = tmp[threadIdx.x] - v;   // exclusive
    if (threadIdx.x == 1023) g_bsums[blockIdx.x] = tmp[1023];
}

__global__ void k_scan2(int nb) {
    __shared__ int s[128];
    int tid = threadIdx.x;
    if (tid < nb) s[tid] = g_bsums[tid];
    __syncthreads();
    if (tid == 0) {
        int run = 0;
        for (int i = 0; i < nb; i++) { int t = s[i]; s[i] = run; run += t; }
    }
    __syncthreads();
    if (tid < nb) g_bsums[tid] = s[tid];
}

__global__ void k_scan3(int n) {
    int gid = blockIdx.x * 1024 + threadIdx.x;
    if (gid < n) {
        int v = g_off[gid] + g_bsums[blockIdx.x];
        g_off[gid] = v;
        g_cur[gid] = v;
    }
}

__global__ void k_scatter(const int* __restrict__ src, const int* __restrict__ dst, int e) {
    int i = blockIdx.x * blockDim.x + threadIdx.x;
    if (i < e) {
        int d = dst[i], s = src[i];
        int p = atomicAdd(&g_cur[d], 1);
        g_csr_src[p] = s;
        g_csr_w[p]   = g_dinv[s] * g_dinv[d];
    }
}

__global__ void k_gbound(const int* __restrict__ batch, int n, int G) {
    int i = blockIdx.x * blockDim.x + threadIdx.x;
    if (i >= n) return;
    int bi = batch[i];
    int bp = (i == 0) ? -1 : batch[i - 1];
    for (int g = bp + 1; g <= bi; g++) g_gstart[g] = i;
    if (i == n - 1)
        for (int g = bi + 1; g <= G; g++) g_gstart[g] = n;
}

__global__ void k_cvtW(const float* __restrict__ W_in, const float* __restrict__ Ws) {
    int i = blockIdx.x * blockDim.x + threadIdx.x;
    if (i >= 5 * HDIM * HDIM) return;
    float w = (i < HDIM * HDIM) ? W_in[i] : Ws[i - HDIM * HDIM];
    __nv_bfloat16 hi = __float2bfloat16_rn(w);
    g_wbf_hi[i] = hi;
    g_wbf_lo[i] = __float2bfloat16_rn(w - __bfloat162float(hi));
}

// ---------------------------------------------------------------------------
// Tensor-core GEMM: C[M,128] = A[M,128] @ (W_hi + W_lo)[128,128]
// ---------------------------------------------------------------------------

__device__ __forceinline__ void ldsm_x4(uint32_t* r, uint32_t addr) {
    asm volatile("ldmatrix.sync.aligned.m8n8.x4.shared.b16 {%0,%1,%2,%3}, [%4];"
        : "=r"(r[0]), "=r"(r[1]), "=r"(r[2]), "=r"(r[3]) : "r"(addr));
}
__device__ __forceinline__ void ldsm_x4_t(uint32_t* r, uint32_t addr) {
    asm volatile("ldmatrix.sync.aligned.m8n8.x4.trans.shared.b16 {%0,%1,%2,%3}, [%4];"
        : "=r"(r[0]), "=r"(r[1]), "=r"(r[2]), "=r"(r[3]) : "r"(addr));
}
__device__ __forceinline__ void mma_bf16(float* c, const uint32_t* a, uint32_t b0, uint32_t b1) {
    asm volatile("mma.sync.aligned.m16n8k16.row.col.f32.bf16.bf16.f32 "
        "{%0,%1,%2,%3}, {%4,%5,%6,%7}, {%8,%9}, {%0,%1,%2,%3};"
        : "+f"(c[0]), "+f"(c[1]), "+f"(c[2]), "+f"(c[3])
        : "r"(a[0]), "r"(a[1]), "r"(a[2]), "r"(a[3]), "r"(b0), "r"(b1));
}

template <int MODE>
__global__ void __launch_bounds__(256)
k_gemm_tc(const float* __restrict__ Afp, int loff,
          const float* __restrict__ bias, int M) {
    __shared__ __nv_bfloat16 As [128 * 64];
    __shared__ __nv_bfloat16 Bhs[64 * 128];
    __shared__ __nv_bfloat16 Bls[64 * 128];
    const __nv_bfloat16* Whi = g_wbf_hi + loff;
    const __nv_bfloat16* Wlo = g_wbf_lo + loff;

    int tid  = threadIdx.x;
    int lane = tid & 31, wid = tid >> 5;
    int wm = wid & 3, wn = wid >> 2;
    int row0 = blockIdx.x * 128;

    uint32_t asb = (uint32_t)__cvta_generic_to_shared(As);
    uint32_t bhb = (uint32_t)__cvta_generic_to_shared(Bhs);
    uint32_t blb = (uint32_t)__cvta_generic_to_shared(Bls);

    float acc[2][8][4];
#pragma unroll
    for (int mi = 0; mi < 2; mi++)
#pragma unroll
        for (int nj = 0; nj < 8; nj++)
#pragma unroll
            for (int q = 0; q < 4; q++) acc[mi][nj][q] = 0.f;

    for (int s = 0; s < 2; s++) {
        int k0 = s * 64;
        if (s) __syncthreads();
#pragma unroll
        for (int i = 0; i < 4; i++) {
            int idx = tid + 256 * i;
            int r = idx >> 3, c = idx & 7;
            int gr = row0 + r;
            uint4 u = make_uint4(0u, 0u, 0u, 0u);
            if (gr < M) {
                if (MODE == 0) {
                    const float4* p = (const float4*)(Afp + (size_t)gr * 128 + k0 + c * 8);
                    float4 f0 = p[0], f1 = p[1];
                    __nv_bfloat162 h0 = __floats2bfloat162_rn(f0.x, f0.y);
                    __nv_bfloat162 h1 = __floats2bfloat162_rn(f0.z, f0.w);
                    __nv_bfloat162 h2 = __floats2bfloat162_rn(f1.x, f1.y);
                    __nv_bfloat162 h3 = __floats2bfloat162_rn(f1.z, f1.w);
                    u.x = *(uint32_t*)&h0; u.y = *(uint32_t*)&h1;
                    u.z = *(uint32_t*)&h2; u.w = *(uint32_t*)&h3;
                } else {
                    u = *(const uint4*)(g_hbf + (size_t)gr * 128 + k0 + c * 8);
                }
            }
            *(uint4*)(As + (size_t)((r << 3) + (c ^ (r & 7))) * 8) = u;
        }
#pragma unroll
        for (int i = 0; i < 4; i++) {
            int idx = tid + 256 * i;
            int k = idx >> 4, c = idx & 15;
            int sw = (c & 8) | ((c & 7) ^ (k & 7));
            *(uint4*)(Bhs + (size_t)(k * 16 + sw) * 8) =
                *(const uint4*)(Whi + (size_t)(k0 + k) * 128 + c * 8);
            *(uint4*)(Bls + (size_t)(k * 16 + sw) * 8) =
                *(const uint4*)(Wlo + (size_t)(k0 + k) * 128 + c * 8);
        }
        __syncthreads();
#pragma unroll
        for (int ks = 0; ks < 4; ks++) {
            uint32_t a[2][4];
#pragma unroll
            for (int mi = 0; mi < 2; mi++) {
                int r  = wm * 32 + mi * 16 + (lane & 15);
                int ch = ks * 2 + (lane >> 4);
                ldsm_x4(a[mi], asb + (uint32_t)((r << 3) + (ch ^ (r & 7))) * 16);
            }
#pragma unroll
            for (int nj = 0; nj < 4; nj++) {
                int k  = ks * 16 + (lane & 15);
                int ch = wn * 8 + nj * 2 + (lane >> 4);
                int sw = (ch & 8) | ((ch & 7) ^ (k & 7));
                uint32_t bh[4], bl[4];
                ldsm_x4_t(bh, bhb + (uint32_t)(k * 16 + sw) * 16);
                ldsm_x4_t(bl, blb + (uint32_t)(k * 16 + sw) * 16);
#pragma unroll
                for (int mi = 0; mi < 2; mi++) {
                    mma_bf16(acc[mi][nj * 2],     a[mi], bh[0], bh[1]);
                    mma_bf16(acc[mi][nj * 2 + 1], a[mi], bh[2], bh[3]);
                    mma_bf16(acc[mi][nj * 2],     a[mi], bl[0], bl[1]);
                    mma_bf16(acc[mi][nj * 2 + 1], a[mi], bl[2], bl[3]);
                }
            }
        }
    }
    int gid = lane >> 2, tig = lane & 3;
    __nv_bfloat16* Out = (MODE == 0) ? g_hbf : g_hwbf;
#pragma unroll
    for (int mi = 0; mi < 2; mi++) {
#pragma unroll
        for (int nj = 0; nj < 8; nj++) {
            int col = wn * 64 + nj * 8 + tig * 2;
            float v0 = acc[mi][nj][0], v1 = acc[mi][nj][1];
            float v2 = acc[mi][nj][2], v3 = acc[mi][nj][3];
            if (MODE == 0) {
                float b0 = bias[col], b1 = bias[col + 1];
                v0 = fmaxf(v0 + b0, 0.f); v1 = fmaxf(v1 + b1, 0.f);
                v2 = fmaxf(v2 + b0, 0.f); v3 = fmaxf(v3 + b1, 0.f);
            }
            int r0 = row0 + wm * 32 + mi * 16 + gid;
            int r1 = r0 + 8;
            if (r0 < M) {
                __nv_bfloat162 p = __floats2bfloat162_rn(v0, v1);
                *(uint32_t*)(Out + (size_t)r0 * 128 + col) = *(uint32_t*)&p;
            }
            if (r1 < M) {
                __nv_bfloat162 p = __floats2bfloat162_rn(v2, v3);
                *(uint32_t*)(Out + (size_t)r1 * 128 + col) = *(uint32_t*)&p;
            }
        }
    }
}

// ---------------------------------------------------------------------------
// bf16 CSR gather + self-loop + bias + BN + relu (fp32 accumulate).
// One warp per node; lane owns 4 features.  CSR entries fetched
// cooperatively (one coalesced load per 32 edges) and shuffled.
// ---------------------------------------------------------------------------
__global__ void k_agg(const float* __restrict__ bias,
                      const float* __restrict__ gamma,
                      const float* __restrict__ beta,
                      const float* __restrict__ rmean,
                      const float* __restrict__ rvar,
                      int n, int e) {
    int w    = (blockIdx.x * blockDim.x + threadIdx.x) >> 5;
    int lane = threadIdx.x & 31;
    if (w >= n) return;
    int f = lane * 4;
    const __nv_bfloat16* hw = g_hwbf;

    float dv = g_dinv[w];
    float ws = dv * dv;
    uint2 us = *(const uint2*)(hw + (size_t)w * HDIM + f);
    float2 s0 = __bfloat1622float2(*(__nv_bfloat162*)&us.x);
    float2 s1 = __bfloat1622float2(*(__nv_bfloat162*)&us.y);
    float ax = s0.x * ws, ay = s0.y * ws, az = s1.x * ws, aw = s1.y * ws;
    float bx = 0.f, by = 0.f, bz = 0.f, bw = 0.f;

    int j0 = g_off[w];
    int j1 = (w + 1 < n) ? g_off[w + 1] : e;

    for (int base = j0; base < j1; base += 32) {
        int cnt = min(32, j1 - base);
        int   se = 0;
        float we = 0.f;
        if (base + lane < j1) {
            se = g_csr_src[base + lane];
            we = g_csr_w[base + lane];
        }
        int k = 0;
        for (; k + 4 <= cnt; k += 4) {
            int   n0 = __shfl_sync(0xffffffffu, se, k);
            float w0 = __shfl_sync(0xffffffffu, we, k);
            int   n1 = __shfl_sync(0xffffffffu, se, k + 1);
            float w1 = __shfl_sync(0xffffffffu, we, k + 1);
            int   n2 = __shfl_sync(0xffffffffu, se, k + 2);
            float w2 = __shfl_sync(0xffffffffu, we, k + 2);
            int   n3 = __shfl_sync(0xffffffffu, se, k + 3);
            float w3 = __shfl_sync(0xffffffffu, we, k + 3);
            uint2 u0 = *(const uint2*)(hw + (size_t)n0 * HDIM + f);
            uint2 u1 = *(const uint2*)(hw + (size_t)n1 * HDIM + f);
            uint2 u2 = *(const uint2*)(hw + (size_t)n2 * HDIM + f);
            uint2 u3 = *(const uint2*)(hw + (size_t)n3 * HDIM + f);
            float2 a0 = __bfloat1622float2(*(__nv_bfloat162*)&u0.x);
            float2 a1 = __bfloat1622float2(*(__nv_bfloat162*)&u0.y);
            ax += a0.x * w0; ay += a0.y * w0; az += a1.x * w0; aw += a1.y * w0;
            float2 c0 = __bfloat1622float2(*(__nv_bfloat162*)&u1.x);
            float2 c1 = __bfloat1622float2(*(__nv_bfloat162*)&u1.y);
            bx += c0.x * w1; by += c0.y * w1; bz += c1.x * w1; bw += c1.y * w1;
            float2 d0 = __bfloat1622float2(*(__nv_bfloat162*)&u2.x);
            float2 d1 = __bfloat1622float2(*(__nv_bfloat162*)&u2.y);
            ax += d0.x * w2; ay += d0.y * w2; az += d1.x * w2; aw += d1.y * w2;
            float2 e0 = __bfloat1622float2(*(__nv_bfloat162*)&u3.x);
            float2 e1 = __bfloat1622float2(*(__nv_bfloat162*)&u3.y);
            bx += e0.x * w3; by += e0.y * w3; bz += e1.x * w3; bw += e1.y * w3;
        }
        for (; k < cnt; k++) {
            int   nk = __shfl_sync(0xffffffffu, se, k);
            float wk = __shfl_sync(0xffffffffu, we, k);
            uint2 u = *(const uint2*)(hw + (size_t)nk * HDIM + f);
            float2 a0 = __bfloat1622float2(*(__nv_bfloat162*)&u.x);
            float2 a1 = __bfloat1622float2(*(__nv_bfloat162*)&u.y);
            ax += a0.x * wk; ay += a0.y * wk; az += a1.x * wk; aw += a1.y * wk;
        }
    }
    ax += bx; ay += by; az += bz; aw += bw;

    float4 bb = *(const float4*)(bias  + f);
    float4 gm = *(const float4*)(gamma + f);
    float4 bt = *(const float4*)(beta  + f);
    float4 rm = *(const float4*)(rmean + f);
    float4 rv = *(const float4*)(rvar  + f);
    float4 o;
    o.x = fmaxf((ax + bb.x - rm.x) * rsqrtf(rv.x + EPSV) * gm.x + bt.x, 0.f);
    o.y = fmaxf((ay + bb.y - rm.y) * rsqrtf(rv.y + EPSV) * gm.y + bt.y, 0.f);
    o.z = fmaxf((az + bb.z - rm.z) * rsqrtf(rv.z + EPSV) * gm.z + bt.z, 0.f);
    o.w = fmaxf((aw + bb.w - rm.w) * rsqrtf(rv.w + EPSV) * gm.w + bt.w, 0.f);
    __nv_bfloat162 q0 = __floats2bfloat162_rn(o.x, o.y);
    __nv_bfloat162 q1 = __floats2bfloat162_rn(o.z, o.w);
    uint2 qo; qo.x = *(uint32_t*)&q0; qo.y = *(uint32_t*)&q1;
    *(uint2*)(g_hbf + (size_t)w * HDIM + f) = qo;
}

// ---------------------------------------------------------------------------
// Fused segmented mean-pool (bf16 input, fp32 accumulate) + MLP head.
// One block (256 threads) per graph.  Deterministic.
// ---------------------------------------------------------------------------
__global__ void k_poolhead(const float* __restrict__ fc1w, const float* __restrict__ fc1b,
                           const float* __restrict__ fc2w, const float* __restrict__ fc2b,
                           float* __restrict__ out) {
    int g   = blockIdx.x;
    int tid = threadIdx.x;          // 256
    int t    = tid & 127;
    int half = tid >> 7;
    __shared__ float ssum[HDIM];
    __shared__ float ge[HDIM];
    __shared__ float h1[64];

    int s0 = g_gstart[g];
    int s1 = g_gstart[g + 1];
    float acc = 0.f;
#pragma unroll 4
    for (int r = s0 + half; r < s1; r += 2)
        acc += __bfloat162float(g_hbf[(size_t)r * HDIM + t]);
    if (half == 1) ssum[t] = acc;
    __syncthreads();
    if (half == 0) {
        float cnt = fmaxf((float)(s1 - s0), 1.f);
        ge[t] = (acc + ssum[t]) / cnt;
    }
    __syncthreads();

    if (tid < 64) {
        float a = fc1b[tid];
#pragma unroll
        for (int i = 0; i < HDIM; i++) a += ge[i] * fc1w[i * 64 + tid];
        h1[tid] = fmaxf(a, 0.f);
    }
    __syncthreads();
    if (tid < 10) {
        float o = fc2b[tid];
#pragma unroll
        for (int jq = 0; jq < 64; jq++) o += h1[jq] * fc2w[jq * 10 + tid];
        out[g * 10 + tid] = o;
    }
}

// ---------------------------------------------------------------------------

extern "C" void kernel_launch(void* const* d_in, const int* in_sizes, int n_in,
                              void* d_out, int out_size) {
    const float* x      = (const float*)d_in[0];
    const int*   eidx   = (const int*)  d_in[1];
    const int*   batch  = (const int*)  d_in[2];
    const float* W_in   = (const float*)d_in[3];
    const float* b_in   = (const float*)d_in[4];
    const float* Ws     = (const float*)d_in[5];
    const float* bs     = (const float*)d_in[6];
    const float* gammas = (const float*)d_in[7];
    const float* betas  = (const float*)d_in[8];
    const float* rmeans = (const float*)d_in[9];
    const float* rvars  = (const float*)d_in[10];
    const float* fc1w   = (const float*)d_in[11];
    const float* fc1b   = (const float*)d_in[12];
    const float* fc2w   = (const float*)d_in[13];
    const float* fc2b   = (const float*)d_in[14];
    float* out = (float*)d_out;

    int N = in_sizes[2];
    int E = in_sizes[1] / 2;
    int G = out_size / 10;
    const int* src = eidx;
    const int* dst = eidx + E;

    const int TB = 256;
    k_zero_deg<<<(N + TB - 1) / TB, TB>>>(N);
    k_hist<<<(E + TB - 1) / TB, TB>>>(dst, E);
    int nb = (N + 1023) / 1024;
    k_scan1<<<nb, 1024>>>(N);
    k_scan2<<<1, 128>>>(nb);
    k_scan3<<<nb, 1024>>>(N);
    k_scatter<<<(E + TB - 1) / TB, TB>>>(src, dst, E);
    k_gbound<<<(N + TB - 1) / TB, TB>>>(batch, N, G);
    k_cvtW<<<(5 * HDIM * HDIM + TB - 1) / TB, TB>>>(W_in, Ws);

    int gblk = (N + 127) / 128;
    k_gemm_tc<0><<<gblk, 256>>>(x, 0, b_in, N);
    for (int l = 0; l < LAYERS; l++) {
        k_gemm_tc<1><<<gblk, 256>>>(nullptr, (1 + l) * HDIM * HDIM, nullptr, N);
        int aggBlocks = (N * 32 + TB - 1) / TB;
        k_agg<<<aggBlocks, TB>>>(bs + l * HDIM, gammas + l * HDIM, betas + l * HDIM,
                                 rmeans + l * HDIM, rvars + l * HDIM, N, E);
    }

    k_poolhead<<<G, 256>>>(fc1w, fc1b, fc2w, fc2b, out);
}

// round 7
// speedup vs baseline: 2.1588x; 1.0212x over previous
#include <cuda_runtime.h>
#include <cuda_bf16.h>
#include <cstdint>

// ---------------------------------------------------------------------------
// BaselineGNN: 4-layer GCN inference.
//   CSR build -> bf16 tensor-core GEMMs (split-weight hi+lo, full-K single
//   stage, 96KB smem) -> bf16 CSR gather (MLP x8) + BN + relu ->
//   deterministic segmented mean-pool + MLP head
// ---------------------------------------------------------------------------

namespace {
constexpr int NMAX  = 100000;
constexpr int EMAX  = 1600000;
constexpr int HDIM  = 128;
constexpr int GMAX  = 256;
constexpr int LAYERS = 4;
constexpr float EPSV = 1e-5f;
constexpr int GEMM_SMEM = 3 * 128 * 128 * 2;   // 98304 B
}

__device__ __nv_bfloat16 g_hbf [NMAX * HDIM];   // h  (GEMM in / agg out / pool in)
__device__ __nv_bfloat16 g_hwbf[NMAX * HDIM];   // hw (GEMM out / agg in)
__device__ __nv_bfloat16 g_wbf_hi[5 * HDIM * HDIM];
__device__ __nv_bfloat16 g_wbf_lo[5 * HDIM * HDIM];
__device__ int   g_degc[NMAX];
__device__ float g_dinv[NMAX];
__device__ int   g_off[NMAX];
__device__ int   g_cur[NMAX];
__device__ int   g_bsums[128];
__device__ int   g_csr_src[EMAX];
__device__ float g_csr_w[EMAX];
__device__ int   g_gstart[GMAX + 1];

// ---------------------------------------------------------------------------

__global__ void k_zero_deg(int n) {
    int i = blockIdx.x * blockDim.x + threadIdx.x;
    if (i < n) g_degc[i] = 0;
}

__global__ void k_hist(const int* __restrict__ dst, int e) {
    int i = blockIdx.x * blockDim.x + threadIdx.x;
    if (i < e) atomicAdd(&g_degc[dst[i]], 1);
}

__global__ void k_scan1(int n) {
    __shared__ int tmp[1024];
    int gid = blockIdx.x * 1024 + threadIdx.x;
    int v = (gid < n) ? g_degc[gid] : 0;
    if (gid < n) g_dinv[gid] = rsqrtf((float)(v + 1));
    tmp[threadIdx.x] = v;
    __syncthreads();
    for (int d = 1; d < 1024; d <<= 1) {
        int t = (threadIdx.x >= d) ? tmp[threadIdx.x - d] : 0;
        __syncthreads();
        tmp[threadIdx.x] += t;
        __syncthreads();
    }
    if (gid < n) g_off[gid] = tmp[threadIdx.x] - v;   // exclusive
    if (threadIdx.x == 1023) g_bsums[blockIdx.x] = tmp[1023];
}

__global__ void k_scan2(int nb) {
    __shared__ int s[128];
    int tid = threadIdx.x;
    if (tid < nb) s[tid] = g_bsums[tid];
    __syncthreads();
    if (tid == 0) {
        int run = 0;
        for (int i = 0; i < nb; i++) { int t = s[i]; s[i] = run; run += t; }
    }
    __syncthreads();
    if (tid < nb) g_bsums[tid] = s[tid];
}

__global__ void k_scan3(int n) {
    int gid = blockIdx.x * 1024 + threadIdx.x;
    if (gid < n) {
        int v = g_off[gid] + g_bsums[blockIdx.x];
        g_off[gid] = v;
        g_cur[gid] = v;
    }
}

__global__ void k_scatter(const int* __restrict__ src, const int* __restrict__ dst, int e) {
    int i = blockIdx.x * blockDim.x + threadIdx.x;
    if (i < e) {
        int d = dst[i], s = src[i];
        int p = atomicAdd(&g_cur[d], 1);
        g_csr_src[p] = s;
        g_csr_w[p]   = g_dinv[s] * g_dinv[d];
    }
}

__global__ void k_gbound(const int* __restrict__ batch, int n, int G) {
    int i = blockIdx.x * blockDim.x + threadIdx.x;
    if (i >= n) return;
    int bi = batch[i];
    int bp = (i == 0) ? -1 : batch[i - 1];
    for (int g = bp + 1; g <= bi; g++) g_gstart[g] = i;
    if (i == n - 1)
        for (int g = bi + 1; g <= G; g++) g_gstart[g] = n;
}

__global__ void k_cvtW(const float* __restrict__ W_in, const float* __restrict__ Ws) {
    int i = blockIdx.x * blockDim.x + threadIdx.x;
    if (i >= 5 * HDIM * HDIM) return;
    float w = (i < HDIM * HDIM) ? W_in[i] : Ws[i - HDIM * HDIM];
    __nv_bfloat16 hi = __float2bfloat16_rn(w);
    g_wbf_hi[i] = hi;
    g_wbf_lo[i] = __float2bfloat16_rn(w - __bfloat162float(hi));
}

// ---------------------------------------------------------------------------
// Tensor-core GEMM: C[M,128] = A[M,128] @ (W_hi + W_lo)[128,128]
// Full K resident: As 32KB + Bh 32KB + Bl 32KB dynamic smem, single sync.
// 8 warps: wm=wid&3 (32 rows), wn=wid>>2 (64 cols).  mma.m16n8k16 bf16->fp32.
// ---------------------------------------------------------------------------

__device__ __forceinline__ void ldsm_x4(uint32_t* r, uint32_t addr) {
    asm volatile("ldmatrix.sync.aligned.m8n8.x4.shared.b16 {%0,%1,%2,%3}, [%4];"
        : "=r"(r[0]), "=r"(r[1]), "=r"(r[2]), "=r"(r[3]) : "r"(addr));
}
__device__ __forceinline__ void ldsm_x4_t(uint32_t* r, uint32_t addr) {
    asm volatile("ldmatrix.sync.aligned.m8n8.x4.trans.shared.b16 {%0,%1,%2,%3}, [%4];"
        : "=r"(r[0]), "=r"(r[1]), "=r"(r[2]), "=r"(r[3]) : "r"(addr));
}
__device__ __forceinline__ void mma_bf16(float* c, const uint32_t* a, uint32_t b0, uint32_t b1) {
    asm volatile("mma.sync.aligned.m16n8k16.row.col.f32.bf16.bf16.f32 "
        "{%0,%1,%2,%3}, {%4,%5,%6,%7}, {%8,%9}, {%0,%1,%2,%3};"
        : "+f"(c[0]), "+f"(c[1]), "+f"(c[2]), "+f"(c[3])
        : "r"(a[0]), "r"(a[1]), "r"(a[2]), "r"(a[3]), "r"(b0), "r"(b1));
}

template <int MODE>
__global__ void __launch_bounds__(256)
k_gemm_tc(const float* __restrict__ Afp, int loff,
          const float* __restrict__ bias, int M) {
    extern __shared__ __nv_bfloat16 smem[];
    __nv_bfloat16* As  = smem;                 // 128 r x 16 chunks(8 bf16)
    __nv_bfloat16* Bhs = smem + 128 * 128;     // 128 k x 16 chunks
    __nv_bfloat16* Bls = smem + 2 * 128 * 128;
    const __nv_bfloat16* Whi = g_wbf_hi + loff;
    const __nv_bfloat16* Wlo = g_wbf_lo + loff;

    int tid  = threadIdx.x;
    int lane = tid & 31, wid = tid >> 5;
    int wm = wid & 3, wn = wid >> 2;
    int row0 = blockIdx.x * 128;

    uint32_t asb = (uint32_t)__cvta_generic_to_shared(As);
    uint32_t bhb = (uint32_t)__cvta_generic_to_shared(Bhs);
    uint32_t blb = (uint32_t)__cvta_generic_to_shared(Bls);

    // ---- load A: 2048 chunks of 16B ----
#pragma unroll
    for (int i = 0; i < 8; i++) {
        int idx = tid + 256 * i;
        int r = idx >> 4, c = idx & 15;
        int gr = row0 + r;
        uint4 u = make_uint4(0u, 0u, 0u, 0u);
        if (gr < M) {
            if (MODE == 0) {
                const float4* p = (const float4*)(Afp + (size_t)gr * 128 + c * 8);
                float4 f0 = p[0], f1 = p[1];
                __nv_bfloat162 h0 = __floats2bfloat162_rn(f0.x, f0.y);
                __nv_bfloat162 h1 = __floats2bfloat162_rn(f0.z, f0.w);
                __nv_bfloat162 h2 = __floats2bfloat162_rn(f1.x, f1.y);
                __nv_bfloat162 h3 = __floats2bfloat162_rn(f1.z, f1.w);
                u.x = *(uint32_t*)&h0; u.y = *(uint32_t*)&h1;
                u.z = *(uint32_t*)&h2; u.w = *(uint32_t*)&h3;
            } else {
                u = *(const uint4*)(g_hbf + (size_t)gr * 128 + c * 8);
            }
        }
        int sw = (c & 8) | ((c & 7) ^ (r & 7));
        *(uint4*)(As + (size_t)(r * 16 + sw) * 8) = u;
    }
    // ---- load B (hi + lo): 2048 chunks each ----
#pragma unroll
    for (int i = 0; i < 8; i++) {
        int idx = tid + 256 * i;
        int k = idx >> 4, c = idx & 15;
        int sw = (c & 8) | ((c & 7) ^ (k & 7));
        *(uint4*)(Bhs + (size_t)(k * 16 + sw) * 8) =
            *(const uint4*)(Whi + (size_t)k * 128 + c * 8);
        *(uint4*)(Bls + (size_t)(k * 16 + sw) * 8) =
            *(const uint4*)(Wlo + (size_t)k * 128 + c * 8);
    }
    __syncthreads();

    float acc[2][8][4];
#pragma unroll
    for (int mi = 0; mi < 2; mi++)
#pragma unroll
        for (int nj = 0; nj < 8; nj++)
#pragma unroll
            for (int q = 0; q < 4; q++) acc[mi][nj][q] = 0.f;

#pragma unroll
    for (int ks = 0; ks < 8; ks++) {
        uint32_t a[2][4];
#pragma unroll
        for (int mi = 0; mi < 2; mi++) {
            int r  = wm * 32 + mi * 16 + (lane & 15);
            int ch = ks * 2 + (lane >> 4);
            int sw = (ch & 8) | ((ch & 7) ^ (r & 7));
            ldsm_x4(a[mi], asb + (uint32_t)(r * 16 + sw) * 16);
        }
#pragma unroll
        for (int nj = 0; nj < 4; nj++) {
            int k  = ks * 16 + (lane & 15);
            int ch = wn * 8 + nj * 2 + (lane >> 4);
            int sw = (ch & 8) | ((ch & 7) ^ (k & 7));
            uint32_t bh[4], bl[4];
            ldsm_x4_t(bh, bhb + (uint32_t)(k * 16 + sw) * 16);
            ldsm_x4_t(bl, blb + (uint32_t)(k * 16 + sw) * 16);
#pragma unroll
            for (int mi = 0; mi < 2; mi++) {
                mma_bf16(acc[mi][nj * 2],     a[mi], bh[0], bh[1]);
                mma_bf16(acc[mi][nj * 2 + 1], a[mi], bh[2], bh[3]);
                mma_bf16(acc[mi][nj * 2],     a[mi], bl[0], bl[1]);
                mma_bf16(acc[mi][nj * 2 + 1], a[mi], bl[2], bl[3]);
            }
        }
    }
    int gid = lane >> 2, tig = lane & 3;
    __nv_bfloat16* Out = (MODE == 0) ? g_hbf : g_hwbf;
#pragma unroll
    for (int mi = 0; mi < 2; mi++) {
#pragma unroll
        for (int nj = 0; nj < 8; nj++) {
            int col = wn * 64 + nj * 8 + tig * 2;
            float v0 = acc[mi][nj][0], v1 = acc[mi][nj][1];
            float v2 = acc[mi][nj][2], v3 = acc[mi][nj][3];
            if (MODE == 0) {
                float b0 = bias[col], b1 = bias[col + 1];
                v0 = fmaxf(v0 + b0, 0.f); v1 = fmaxf(v1 + b1, 0.f);
                v2 = fmaxf(v2 + b0, 0.f); v3 = fmaxf(v3 + b1, 0.f);
            }
            int r0 = row0 + wm * 32 + mi * 16 + gid;
            int r1 = r0 + 8;
            if (r0 < M) {
                __nv_bfloat162 p = __floats2bfloat162_rn(v0, v1);
                *(uint32_t*)(Out + (size_t)r0 * 128 + col) = *(uint32_t*)&p;
            }
            if (r1 < M) {
                __nv_bfloat162 p = __floats2bfloat162_rn(v2, v3);
                *(uint32_t*)(Out + (size_t)r1 * 128 + col) = *(uint32_t*)&p;
            }
        }
    }
}

// ---------------------------------------------------------------------------
// bf16 CSR gather + self-loop + bias + BN + relu (fp32 accumulate).
// One warp per node; lane owns 4 features.  Gather loop unrolled x8 (MLP=8),
// 32-bit addressing.
// ---------------------------------------------------------------------------
__device__ __forceinline__ void acc_edge(const __nv_bfloat16* hw, unsigned off,
                                         float wt, float& x, float& y,
                                         float& z, float& w) {
    uint2 u = *(const uint2*)(hw + off);
    float2 a0 = __bfloat1622float2(*(__nv_bfloat162*)&u.x);
    float2 a1 = __bfloat1622float2(*(__nv_bfloat162*)&u.y);
    x += a0.x * wt; y += a0.y * wt; z += a1.x * wt; w += a1.y * wt;
}

__global__ void k_agg(const float* __restrict__ bias,
                      const float* __restrict__ gamma,
                      const float* __restrict__ beta,
                      const float* __restrict__ rmean,
                      const float* __restrict__ rvar,
                      int n, int e) {
    int w    = (blockIdx.x * blockDim.x + threadIdx.x) >> 5;
    int lane = threadIdx.x & 31;
    if (w >= n) return;
    unsigned f = (unsigned)lane * 4;
    const __nv_bfloat16* hw = g_hwbf;

    float dv = g_dinv[w];
    float ws = dv * dv;
    float ax, ay, az, aw;
    {
        uint2 us = *(const uint2*)(hw + ((unsigned)w << 7) + f);
        float2 s0 = __bfloat1622float2(*(__nv_bfloat162*)&us.x);
        float2 s1 = __bfloat1622float2(*(__nv_bfloat162*)&us.y);
        ax = s0.x * ws; ay = s0.y * ws; az = s1.x * ws; aw = s1.y * ws;
    }
    float bx = 0.f, by = 0.f, bz = 0.f, bw = 0.f;

    int j0 = g_off[w];
    int j1 = (w + 1 < n) ? g_off[w + 1] : e;
    int j = j0;
    for (; j + 8 <= j1; j += 8) {
        unsigned o0 = ((unsigned)g_csr_src[j]     << 7) + f; float w0 = g_csr_w[j];
        unsigned o1 = ((unsigned)g_csr_src[j + 1] << 7) + f; float w1 = g_csr_w[j + 1];
        unsigned o2 = ((unsigned)g_csr_src[j + 2] << 7) + f; float w2 = g_csr_w[j + 2];
        unsigned o3 = ((unsigned)g_csr_src[j + 3] << 7) + f; float w3 = g_csr_w[j + 3];
        unsigned o4 = ((unsigned)g_csr_src[j + 4] << 7) + f; float w4 = g_csr_w[j + 4];
        unsigned o5 = ((unsigned)g_csr_src[j + 5] << 7) + f; float w5 = g_csr_w[j + 5];
        unsigned o6 = ((unsigned)g_csr_src[j + 6] << 7) + f; float w6 = g_csr_w[j + 6];
        unsigned o7 = ((unsigned)g_csr_src[j + 7] << 7) + f; float w7 = g_csr_w[j + 7];
        acc_edge(hw, o0, w0, ax, ay, az, aw);
        acc_edge(hw, o1, w1, bx, by, bz, bw);
        acc_edge(hw, o2, w2, ax, ay, az, aw);
        acc_edge(hw, o3, w3, bx, by, bz, bw);
        acc_edge(hw, o4, w4, ax, ay, az, aw);
        acc_edge(hw, o5, w5, bx, by, bz, bw);
        acc_edge(hw, o6, w6, ax, ay, az, aw);
        acc_edge(hw, o7, w7, bx, by, bz, bw);
    }
    for (; j < j1; j++) {
        unsigned o = ((unsigned)g_csr_src[j] << 7) + f;
        acc_edge(hw, o, g_csr_w[j], ax, ay, az, aw);
    }
    ax += bx; ay += by; az += bz; aw += bw;

    float4 bb = *(const float4*)(bias  + f);
    float4 gm = *(const float4*)(gamma + f);
    float4 bt = *(const float4*)(beta  + f);
    float4 rm = *(const float4*)(rmean + f);
    float4 rv = *(const float4*)(rvar  + f);
    float4 o;
    o.x = fmaxf((ax + bb.x - rm.x) * rsqrtf(rv.x + EPSV) * gm.x + bt.x, 0.f);
    o.y = fmaxf((ay + bb.y - rm.y) * rsqrtf(rv.y + EPSV) * gm.y + bt.y, 0.f);
    o.z = fmaxf((az + bb.z - rm.z) * rsqrtf(rv.z + EPSV) * gm.z + bt.z, 0.f);
    o.w = fmaxf((aw + bb.w - rm.w) * rsqrtf(rv.w + EPSV) * gm.w + bt.w, 0.f);
    __nv_bfloat162 q0 = __floats2bfloat162_rn(o.x, o.y);
    __nv_bfloat162 q1 = __floats2bfloat162_rn(o.z, o.w);
    uint2 qo; qo.x = *(uint32_t*)&q0; qo.y = *(uint32_t*)&q1;
    *(uint2*)(g_hbf + ((unsigned)w << 7) + f) = qo;
}

// ---------------------------------------------------------------------------
// Fused segmented mean-pool (bf16 input, fp32 accumulate) + MLP head.
// ---------------------------------------------------------------------------
__global__ void k_poolhead(const float* __restrict__ fc1w, const float* __restrict__ fc1b,
                           const float* __restrict__ fc2w, const float* __restrict__ fc2b,
                           float* __restrict__ out) {
    int g   = blockIdx.x;
    int tid = threadIdx.x;          // 256
    int t    = tid & 127;
    int half = tid >> 7;
    __shared__ float ssum[HDIM];
    __shared__ float ge[HDIM];
    __shared__ float h1[64];

    int s0 = g_gstart[g];
    int s1 = g_gstart[g + 1];
    float acc = 0.f;
#pragma unroll 4
    for (int r = s0 + half; r < s1; r += 2)
        acc += __bfloat162float(g_hbf[(size_t)r * HDIM + t]);
    if (half == 1) ssum[t] = acc;
    __syncthreads();
    if (half == 0) {
        float cnt = fmaxf((float)(s1 - s0), 1.f);
        ge[t] = (acc + ssum[t]) / cnt;
    }
    __syncthreads();

    if (tid < 64) {
        float a = fc1b[tid];
#pragma unroll
        for (int i = 0; i < HDIM; i++) a += ge[i] * fc1w[i * 64 + tid];
        h1[tid] = fmaxf(a, 0.f);
    }
    __syncthreads();
    if (tid < 10) {
        float o = fc2b[tid];
#pragma unroll
        for (int jq = 0; jq < 64; jq++) o += h1[jq] * fc2w[jq * 10 + tid];
        out[g * 10 + tid] = o;
    }
}

// ---------------------------------------------------------------------------

extern "C" void kernel_launch(void* const* d_in, const int* in_sizes, int n_in,
                              void* d_out, int out_size) {
    const float* x      = (const float*)d_in[0];
    const int*   eidx   = (const int*)  d_in[1];
    const int*   batch  = (const int*)  d_in[2];
    const float* W_in   = (const float*)d_in[3];
    const float* b_in   = (const float*)d_in[4];
    const float* Ws     = (const float*)d_in[5];
    const float* bs     = (const float*)d_in[6];
    const float* gammas = (const float*)d_in[7];
    const float* betas  = (const float*)d_in[8];
    const float* rmeans = (const float*)d_in[9];
    const float* rvars  = (const float*)d_in[10];
    const float* fc1w   = (const float*)d_in[11];
    const float* fc1b   = (const float*)d_in[12];
    const float* fc2w   = (const float*)d_in[13];
    const float* fc2b   = (const float*)d_in[14];
    float* out = (float*)d_out;

    int N = in_sizes[2];
    int E = in_sizes[1] / 2;
    int G = out_size / 10;
    const int* src = eidx;
    const int* dst = eidx + E;

    cudaFuncSetAttribute(k_gemm_tc<0>, cudaFuncAttributeMaxDynamicSharedMemorySize, GEMM_SMEM);
    cudaFuncSetAttribute(k_gemm_tc<1>, cudaFuncAttributeMaxDynamicSharedMemorySize, GEMM_SMEM);

    const int TB = 256;
    k_zero_deg<<<(N + TB - 1) / TB, TB>>>(N);
    k_hist<<<(E + TB - 1) / TB, TB>>>(dst, E);
    int nb = (N + 1023) / 1024;
    k_scan1<<<nb, 1024>>>(N);
    k_scan2<<<1, 128>>>(nb);
    k_scan3<<<nb, 1024>>>(N);
    k_scatter<<<(E + TB - 1) / TB, TB>>>(src, dst, E);
    k_gbound<<<(N + TB - 1) / TB, TB>>>(batch, N, G);
    k_cvtW<<<(5 * HDIM * HDIM + TB - 1) / TB, TB>>>(W_in, Ws);

    int gblk = (N + 127) / 128;
    k_gemm_tc<0><<<gblk, 256, GEMM_SMEM>>>(x, 0, b_in, N);
    for (int l = 0; l < LAYERS; l++) {
        k_gemm_tc<1><<<gblk, 256, GEMM_SMEM>>>(nullptr, (1 + l) * HDIM * HDIM, nullptr, N);
        int aggBlocks = (N * 32 + TB - 1) / TB;
        k_agg<<<aggBlocks, TB>>>(bs + l * HDIM, gammas + l * HDIM, betas + l * HDIM,
                                 rmeans + l * HDIM, rvars + l * HDIM, N, E);
    }

    k_poolhead<<<G, 256>>>(fc1w, fc1b, fc2w, fc2b, out);
}